// round 7
// baseline (speedup 1.0000x reference)
#include <cuda_runtime.h>
#include <cstdint>
#include <math_constants.h>

// Sparsemax along last dim (d = 1024), one warp per row, row in registers.
// Exact threshold via Michelot fixed-point warm-started at tau0 = max(z)-1
// (valid: tau* >= max-1, since sum(p)=1 forces p_max <= 1).
// Step 1 of Michelot runs on the full register file (ILP-friendly, no serial
// chain) -> tau1. Actives at tau1 (~k* values) are binned into 3 registers
// per lane; remaining iterations run on those slots. Rare overflow falls
// back to full-register iteration. No smem, no block barriers.
// __launch_bounds__(.., 6) caps regs to lift occupancy to 6 blocks/SM.

constexpr int D   = 1024;
constexpr int WPB = 8;               // warps (rows) per block
constexpr int TPB = WPB * 32;

// Order-preserving float<->int mapping (valid for non-NaN inputs).
__device__ __forceinline__ int f2i_mono(float f) {
    int i = __float_as_int(f);
    return i >= 0 ? i : i ^ 0x7fffffff;
}
__device__ __forceinline__ float i2f_mono(int i) {
    return __int_as_float(i >= 0 ? i : i ^ 0x7fffffff);
}

__device__ __forceinline__ float warp_sum(float x) {
#pragma unroll
    for (int o = 16; o > 0; o >>= 1)
        x += __shfl_xor_sync(0xffffffffu, x, o);
    return x;
}

__global__ void __launch_bounds__(TPB, 6)
sparsemax_kernel(const float* __restrict__ z, float* __restrict__ p, int rows) {
    const int wl   = threadIdx.x >> 5;
    const int lane = threadIdx.x & 31;
    const int row  = blockIdx.x * WPB + wl;
    if (row >= rows) return;

    const float* zr = z + (size_t)row * D;
    float*       pr = p + (size_t)row * D;

    // ---- load row: 8 x float4 per lane, coalesced, streaming ----
    float v[32];
#pragma unroll
    for (int j = 0; j < 8; j++) {
        float4 t = __ldcs(reinterpret_cast<const float4*>(zr + j * 128 + lane * 4));
        v[4 * j + 0] = t.x;
        v[4 * j + 1] = t.y;
        v[4 * j + 2] = t.z;
        v[4 * j + 3] = t.w;
    }

    // ---- row max: register tree (ILP) + single-instruction int redux ----
    float m = v[0];
#pragma unroll
    for (int i = 1; i < 32; i++) m = fmaxf(m, v[i]);
    m = i2f_mono(__reduce_max_sync(0xffffffffu, f2i_mono(m)));

    float tau = m - 1.0f;

    // ---- Michelot step 1 on the full register file (pure ILP, no chain) ----
    {
        float s = 0.0f, kk = 0.0f;
#pragma unroll
        for (int i = 0; i < 32; i++) {
            bool a = v[i] > tau;
            s  += a ? v[i] : 0.0f;
            kk += a ? 1.0f : 0.0f;
        }
        s  = warp_sum(s);
        kk = warp_sum(kk);
        tau = (s - 1.0f) / kk;       // kk >= 1 always (max > tau0)
    }

    // ---- bin actives at tau1 (close to final support) into 3 regs/lane ----
    float x0 = -CUDART_INF_F, x1 = -CUDART_INF_F, x2 = -CUDART_INF_F;
    int lc = 0;
#pragma unroll
    for (int i = 0; i < 32; i++) {
        if (v[i] > tau) {
            if (lc == 0)      x0 = v[i];
            else if (lc == 1) x1 = v[i];
            else if (lc == 2) x2 = v[i];
            lc++;
        }
    }
    const bool overflow = __ballot_sync(0xffffffffu, lc > 3) != 0u;

    // ---- remaining Michelot fixed-point iterations ----
    if (!overflow) {
        // common case: all actives live in x0..x2 across the warp
#pragma unroll 1
        for (int it = 0; it < 40; it++) {
            bool a0 = x0 > tau, a1 = x1 > tau, a2 = x2 > tau;
            int k = __popc(__ballot_sync(0xffffffffu, a0))
                  + __popc(__ballot_sync(0xffffffffu, a1))
                  + __popc(__ballot_sync(0xffffffffu, a2));   // k >= 1 always
            float s = (a0 ? x0 : 0.0f) + (a1 ? x1 : 0.0f) + (a2 ? x2 : 0.0f);
            s = warp_sum(s);
            float nt = (s - 1.0f) / (float)k;
            if (nt == tau) break;   // exact fixed point = sparsemax threshold
            tau = nt;
        }
    } else {
        // rare fallback: iterate over the full register-resident row
#pragma unroll 1
        for (int it = 0; it < 64; it++) {
            float s = 0.0f, kk = 0.0f;
#pragma unroll
            for (int i = 0; i < 32; i++) {
                bool a = v[i] > tau;
                s  += a ? v[i] : 0.0f;
                kk += a ? 1.0f : 0.0f;
            }
            s  = warp_sum(s);
            kk = warp_sum(kk);
            float nt = (s - 1.0f) / kk;
            if (nt == tau) break;
            tau = nt;
        }
    }

    // ---- write p = relu(z - tau), coalesced float4 streaming stores ----
#pragma unroll
    for (int j = 0; j < 8; j++) {
        float4 t;
        t.x = fmaxf(v[4 * j + 0] - tau, 0.0f);
        t.y = fmaxf(v[4 * j + 1] - tau, 0.0f);
        t.z = fmaxf(v[4 * j + 2] - tau, 0.0f);
        t.w = fmaxf(v[4 * j + 3] - tau, 0.0f);
        __stcs(reinterpret_cast<float4*>(pr + j * 128 + lane * 4), t);
    }
}

extern "C" void kernel_launch(void* const* d_in, const int* in_sizes, int n_in,
                              void* d_out, int out_size) {
    const float* z = (const float*)d_in[0];
    float* p = (float*)d_out;
    const int rows = in_sizes[0] / D;                  // 32768
    const int grid = (rows + WPB - 1) / WPB;           // 4096
    sparsemax_kernel<<<grid, TPB>>>(z, p, rows);
}